// round 16
// baseline (speedup 1.0000x reference)
#include <cuda_runtime.h>

// diff[k] = (f[k-3] - f[k+2]) / 5 with zero-padding outside [0,n)
// change[k] = diff[k]^2 for k>=1, change[0] = 0
// out[k] = (1 - change[k]/S)^5 * f[k],  S = sum(change)
//
// Champion structure (R13/R15) with ONE change: phase-2 stores use default
// write-back policy instead of __stcs (evict-first). Rationale: evict-first
// forces the 64MB output to hit DRAM during phase2 (the write-direction
// floor); default policy leaves lines dirty in L2 so their writebacks drain
// during the NEXT graph replay's read-only phase1, whose write direction is
// idle -- overlapping the two DRAM directions across replay boundaries.

#define TPB 256
#define VPT 5                              // float4 vectors per thread (batched)
#define EPB (TPB * VPT * 4)                // 5120 elems per super-chunk
#define GRID 888                           // 148 SMs x 6 blocks, fully resident
#define FULL 0xffffffffu

__device__ float g_part[GRID];
__device__ float g_invS;
__device__ unsigned long long g_arrive  = 0;   // monotonic across graph replays
__device__ unsigned long long g_release = 0;

__global__ void __launch_bounds__(TPB, 6) k_fused(const float* __restrict__ f,
                                                  float* __restrict__ out, int n) {
    const int tid  = threadIdx.x;
    const int lane = tid & 31;
    const int warp = tid >> 5;
    const int nchunks = (n + EPB - 1) / EPB;

    __shared__ float  s_w[TPB / 32];
    __shared__ double s_d[TPB / 32];
    __shared__ float  s_invS;
    __shared__ int    s_last;

    // ======================= phase 1: sum of change =======================
    float acc = 0.0f;
    for (int sc = blockIdx.x; sc < nchunks; sc += GRID) {
        const int base = sc * EPB;
        if (sc > 0 && base + EPB + 5 <= n) {
            // interior: batch 5 main loads (deep MLP), halo via shuffle
            float4 c[VPT];
            #pragma unroll
            for (int j = 0; j < VPT; j++) {
                const int v = base + j * (TPB * 4) + tid * 4;
                c[j] = __ldg(reinterpret_cast<const float4*>(f + v));
            }
            #pragma unroll
            for (int j = 0; j < VPT; j++) {
                const int v = base + j * (TPB * 4) + tid * 4;
                float m3 = __shfl_up_sync(FULL, c[j].y, 1);
                float m2 = __shfl_up_sync(FULL, c[j].z, 1);
                float m1 = __shfl_up_sync(FULL, c[j].w, 1);
                float p4 = __shfl_down_sync(FULL, c[j].x, 1);
                float p5 = __shfl_down_sync(FULL, c[j].y, 1);
                if (lane == 0) {
                    m3 = __ldg(f + v - 3);
                    m2 = __ldg(f + v - 2);
                    m1 = __ldg(f + v - 1);
                }
                if (lane == 31) {
                    p4 = __ldg(f + v + 4);
                    p5 = __ldg(f + v + 5);
                }
                float d0 = (m3     - c[j].z) * 0.2f;
                float d1 = (m2     - c[j].w) * 0.2f;
                float d2 = (m1     - p4    ) * 0.2f;
                float d3 = (c[j].x - p5    ) * 0.2f;
                acc += d0 * d0 + d1 * d1 + d2 * d2 + d3 * d3;
            }
        } else {
            #pragma unroll
            for (int j = 0; j < VPT; j++) {
                const int v = base + j * (TPB * 4) + tid * 4;
                if (v + 3 < n) {
                    float4 c = __ldg(reinterpret_cast<const float4*>(f + v));
                    float m3 = (v >= 3)     ? __ldg(f + v - 3) : 0.0f;
                    float m2 = (v >= 2)     ? __ldg(f + v - 2) : 0.0f;
                    float m1 = (v >= 1)     ? __ldg(f + v - 1) : 0.0f;
                    float p4 = (v + 4 < n)  ? __ldg(f + v + 4) : 0.0f;
                    float p5 = (v + 5 < n)  ? __ldg(f + v + 5) : 0.0f;
                    float d0 = (m3  - c.z) * 0.2f;
                    float d1 = (m2  - c.w) * 0.2f;
                    float d2 = (m1  - p4 ) * 0.2f;
                    float d3 = (c.x - p5 ) * 0.2f;
                    float c0 = (v == 0) ? 0.0f : d0 * d0;
                    acc += c0 + d1 * d1 + d2 * d2 + d3 * d3;
                } else if (v < n) {
                    for (int k = v; k < n; k++) {
                        float l = (k >= 3)    ? __ldg(f + k - 3) : 0.0f;
                        float r = (k + 2 < n) ? __ldg(f + k + 2) : 0.0f;
                        float d = (l - r) * 0.2f;
                        if (k != 0) acc += d * d;
                    }
                }
            }
        }
    }

    #pragma unroll
    for (int o = 16; o > 0; o >>= 1)
        acc += __shfl_down_sync(FULL, acc, o);
    if (lane == 0) s_w[warp] = acc;
    __syncthreads();

    // ======================= grid sync (generation counters) ==============
    if (tid == 0) {
        float b = 0.0f;
        #pragma unroll
        for (int w = 0; w < TPB / 32; w++) b += s_w[w];
        g_part[blockIdx.x] = b;
        __threadfence();
        unsigned long long ticket = atomicAdd(&g_arrive, 1ULL);
        unsigned long long gen = ticket / (unsigned long long)GRID;
        int last = ((int)(ticket % (unsigned long long)GRID) == GRID - 1);
        s_last = last;
        if (!last) {
            while (*((volatile unsigned long long*)&g_release) < gen + 1ULL) {
                __nanosleep(32);
            }
            __threadfence();
            s_invS = *((volatile float*)&g_invS);
        }
    }
    __syncthreads();

    if (s_last) {   // block-uniform
        __threadfence();
        double a = 0.0;
        for (int i = tid; i < GRID; i += TPB)
            a += (double)g_part[i];
        #pragma unroll
        for (int o = 16; o > 0; o >>= 1)
            a += __shfl_down_sync(FULL, a, o);
        if (lane == 0) s_d[warp] = a;
        __syncthreads();
        if (tid == 0) {
            double s = 0.0;
            #pragma unroll
            for (int w = 0; w < TPB / 32; w++) s += s_d[w];
            float inv = (float)(1.0 / s);
            s_invS = inv;
            *((volatile float*)&g_invS) = inv;
            __threadfence();
            atomicAdd(&g_release, 1ULL);
        }
        __syncthreads();
    }

    const float invS = s_invS;

    // ======================= phase 2: scale + write ========================
    // Same block-stride chunks as phase 1, REVERSE order (warm cache first).
    // Default write-back stores: leave output dirty in L2, defer writeback.
    const int nmine = (nchunks > blockIdx.x)
                    ? ((nchunks - blockIdx.x + GRID - 1) / GRID) : 0;
    for (int i = nmine - 1; i >= 0; i--) {
        const int sc = blockIdx.x + i * GRID;
        const int base = sc * EPB;
        if (sc > 0 && base + EPB + 5 <= n) {
            float4 c[VPT];
            #pragma unroll
            for (int j = 0; j < VPT; j++) {
                const int v = base + j * (TPB * 4) + tid * 4;
                c[j] = __ldg(reinterpret_cast<const float4*>(f + v));
            }
            #pragma unroll
            for (int j = 0; j < VPT; j++) {
                const int v = base + j * (TPB * 4) + tid * 4;
                float m3 = __shfl_up_sync(FULL, c[j].y, 1);
                float m2 = __shfl_up_sync(FULL, c[j].z, 1);
                float m1 = __shfl_up_sync(FULL, c[j].w, 1);
                float p4 = __shfl_down_sync(FULL, c[j].x, 1);
                float p5 = __shfl_down_sync(FULL, c[j].y, 1);
                if (lane == 0) {
                    m3 = __ldg(f + v - 3);
                    m2 = __ldg(f + v - 2);
                    m1 = __ldg(f + v - 1);
                }
                if (lane == 31) {
                    p4 = __ldg(f + v + 4);
                    p5 = __ldg(f + v + 5);
                }
                float d0 = (m3     - c[j].z) * 0.2f;
                float d1 = (m2     - c[j].w) * 0.2f;
                float d2 = (m1     - p4    ) * 0.2f;
                float d3 = (c[j].x - p5    ) * 0.2f;
                float t0 = 1.0f - d0 * d0 * invS;
                float t1 = 1.0f - d1 * d1 * invS;
                float t2 = 1.0f - d2 * d2 * invS;
                float t3 = 1.0f - d3 * d3 * invS;
                float q0 = t0 * t0, q1 = t1 * t1, q2 = t2 * t2, q3 = t3 * t3;
                float4 o;
                o.x = q0 * q0 * t0 * c[j].x;
                o.y = q1 * q1 * t1 * c[j].y;
                o.z = q2 * q2 * t2 * c[j].z;
                o.w = q3 * q3 * t3 * c[j].w;
                *reinterpret_cast<float4*>(out + v) = o;   // default write-back
            }
        } else {
            #pragma unroll
            for (int j = 0; j < VPT; j++) {
                const int v = base + j * (TPB * 4) + tid * 4;
                if (v + 3 < n) {
                    float4 c = __ldg(reinterpret_cast<const float4*>(f + v));
                    float m3 = (v >= 3)    ? __ldg(f + v - 3) : 0.0f;
                    float m2 = (v >= 2)    ? __ldg(f + v - 2) : 0.0f;
                    float m1 = (v >= 1)    ? __ldg(f + v - 1) : 0.0f;
                    float p4 = (v + 4 < n) ? __ldg(f + v + 4) : 0.0f;
                    float p5 = (v + 5 < n) ? __ldg(f + v + 5) : 0.0f;
                    float d0 = (m3  - c.z) * 0.2f;
                    float d1 = (m2  - c.w) * 0.2f;
                    float d2 = (m1  - p4 ) * 0.2f;
                    float d3 = (c.x - p5 ) * 0.2f;
                    float c0 = (v == 0) ? 0.0f : d0 * d0 * invS;
                    float t0 = 1.0f - c0;
                    float t1 = 1.0f - d1 * d1 * invS;
                    float t2 = 1.0f - d2 * d2 * invS;
                    float t3 = 1.0f - d3 * d3 * invS;
                    float q0 = t0 * t0, q1 = t1 * t1, q2 = t2 * t2, q3 = t3 * t3;
                    float4 o;
                    o.x = q0 * q0 * t0 * c.x;
                    o.y = q1 * q1 * t1 * c.y;
                    o.z = q2 * q2 * t2 * c.z;
                    o.w = q3 * q3 * t3 * c.w;
                    *reinterpret_cast<float4*>(out + v) = o;
                } else if (v < n) {
                    for (int k = v; k < n; k++) {
                        float l = (k >= 3)    ? __ldg(f + k - 3) : 0.0f;
                        float r = (k + 2 < n) ? __ldg(f + k + 2) : 0.0f;
                        float d = (l - r) * 0.2f;
                        float ch = (k == 0) ? 0.0f : d * d * invS;
                        float t = 1.0f - ch;
                        float q = t * t;
                        out[k] = q * q * t * __ldg(f + k);
                    }
                }
            }
        }
    }
}

// ---------------------------------------------------------------- launch
extern "C" void kernel_launch(void* const* d_in, const int* in_sizes, int n_in,
                              void* d_out, int out_size) {
    const float* f = (const float*)d_in[0];
    float* out = (float*)d_out;
    int n = in_sizes[0];

    k_fused<<<GRID, TPB>>>(f, out, n);
}

// round 17
// speedup vs baseline: 1.1199x; 1.1199x over previous
#include <cuda_runtime.h>

// diff[k] = (f[k-3] - f[k+2]) / 5 with zero-padding outside [0,n)
// change[k] = diff[k]^2 for k>=1, change[0] = 0
// out[k] = (1 - change[k]/S)^5 * f[k],  S = sum(change)
//
// CERTIFIED FINAL (R13/R15 champion, reproduced at 32.83/32.96 us):
// single persistent kernel, block-stride 5120-elem super-chunks.
//   phase1: partial sums; per chunk, 5 float4 loads batched back-to-back
//           (deep MLP), stencil halo via warp shuffles (edge lanes fall back
//           to L1-resident scalar loads).
//   grid sync: monotonic generation counters (graph-replay safe, no reset
//           kernel); last-arriving block reduces 888 partials in double and
//           publishes 1/S.
//   phase2: SAME chunks in REVERSE order (block's most recently read chunk
//           first, lines L1/L2-hot), evict-first streaming stores (__stcs) —
//           empirically beats write-back (+4us) and write-through (+4us).

#define TPB 256
#define VPT 5                              // float4 vectors per thread (batched)
#define EPB (TPB * VPT * 4)                // 5120 elems per super-chunk
#define GRID 888                           // 148 SMs x 6 blocks, fully resident
#define FULL 0xffffffffu

__device__ float g_part[GRID];
__device__ float g_invS;
__device__ unsigned long long g_arrive  = 0;   // monotonic across graph replays
__device__ unsigned long long g_release = 0;

__global__ void __launch_bounds__(TPB, 6) k_fused(const float* __restrict__ f,
                                                  float* __restrict__ out, int n) {
    const int tid  = threadIdx.x;
    const int lane = tid & 31;
    const int warp = tid >> 5;
    const int nchunks = (n + EPB - 1) / EPB;

    __shared__ float  s_w[TPB / 32];
    __shared__ double s_d[TPB / 32];
    __shared__ float  s_invS;
    __shared__ int    s_last;

    // ======================= phase 1: sum of change =======================
    float acc = 0.0f;
    for (int sc = blockIdx.x; sc < nchunks; sc += GRID) {
        const int base = sc * EPB;
        if (sc > 0 && base + EPB + 5 <= n) {
            // interior: batch 5 main loads (deep MLP), halo via shuffle
            float4 c[VPT];
            #pragma unroll
            for (int j = 0; j < VPT; j++) {
                const int v = base + j * (TPB * 4) + tid * 4;
                c[j] = __ldg(reinterpret_cast<const float4*>(f + v));
            }
            #pragma unroll
            for (int j = 0; j < VPT; j++) {
                const int v = base + j * (TPB * 4) + tid * 4;
                float m3 = __shfl_up_sync(FULL, c[j].y, 1);
                float m2 = __shfl_up_sync(FULL, c[j].z, 1);
                float m1 = __shfl_up_sync(FULL, c[j].w, 1);
                float p4 = __shfl_down_sync(FULL, c[j].x, 1);
                float p5 = __shfl_down_sync(FULL, c[j].y, 1);
                if (lane == 0) {
                    m3 = __ldg(f + v - 3);
                    m2 = __ldg(f + v - 2);
                    m1 = __ldg(f + v - 1);
                }
                if (lane == 31) {
                    p4 = __ldg(f + v + 4);
                    p5 = __ldg(f + v + 5);
                }
                float d0 = (m3     - c[j].z) * 0.2f;
                float d1 = (m2     - c[j].w) * 0.2f;
                float d2 = (m1     - p4    ) * 0.2f;
                float d3 = (c[j].x - p5    ) * 0.2f;
                acc += d0 * d0 + d1 * d1 + d2 * d2 + d3 * d3;
            }
        } else {
            #pragma unroll
            for (int j = 0; j < VPT; j++) {
                const int v = base + j * (TPB * 4) + tid * 4;
                if (v + 3 < n) {
                    float4 c = __ldg(reinterpret_cast<const float4*>(f + v));
                    float m3 = (v >= 3)     ? __ldg(f + v - 3) : 0.0f;
                    float m2 = (v >= 2)     ? __ldg(f + v - 2) : 0.0f;
                    float m1 = (v >= 1)     ? __ldg(f + v - 1) : 0.0f;
                    float p4 = (v + 4 < n)  ? __ldg(f + v + 4) : 0.0f;
                    float p5 = (v + 5 < n)  ? __ldg(f + v + 5) : 0.0f;
                    float d0 = (m3  - c.z) * 0.2f;
                    float d1 = (m2  - c.w) * 0.2f;
                    float d2 = (m1  - p4 ) * 0.2f;
                    float d3 = (c.x - p5 ) * 0.2f;
                    float c0 = (v == 0) ? 0.0f : d0 * d0;
                    acc += c0 + d1 * d1 + d2 * d2 + d3 * d3;
                } else if (v < n) {
                    for (int k = v; k < n; k++) {
                        float l = (k >= 3)    ? __ldg(f + k - 3) : 0.0f;
                        float r = (k + 2 < n) ? __ldg(f + k + 2) : 0.0f;
                        float d = (l - r) * 0.2f;
                        if (k != 0) acc += d * d;
                    }
                }
            }
        }
    }

    #pragma unroll
    for (int o = 16; o > 0; o >>= 1)
        acc += __shfl_down_sync(FULL, acc, o);
    if (lane == 0) s_w[warp] = acc;
    __syncthreads();

    // ======================= grid sync (generation counters) ==============
    if (tid == 0) {
        float b = 0.0f;
        #pragma unroll
        for (int w = 0; w < TPB / 32; w++) b += s_w[w];
        g_part[blockIdx.x] = b;
        __threadfence();
        unsigned long long ticket = atomicAdd(&g_arrive, 1ULL);
        unsigned long long gen = ticket / (unsigned long long)GRID;
        int last = ((int)(ticket % (unsigned long long)GRID) == GRID - 1);
        s_last = last;
        if (!last) {
            while (*((volatile unsigned long long*)&g_release) < gen + 1ULL) {
                __nanosleep(32);
            }
            __threadfence();
            s_invS = *((volatile float*)&g_invS);
        }
    }
    __syncthreads();

    if (s_last) {   // block-uniform
        __threadfence();
        double a = 0.0;
        for (int i = tid; i < GRID; i += TPB)
            a += (double)g_part[i];
        #pragma unroll
        for (int o = 16; o > 0; o >>= 1)
            a += __shfl_down_sync(FULL, a, o);
        if (lane == 0) s_d[warp] = a;
        __syncthreads();
        if (tid == 0) {
            double s = 0.0;
            #pragma unroll
            for (int w = 0; w < TPB / 32; w++) s += s_d[w];
            float inv = (float)(1.0 / s);
            s_invS = inv;
            *((volatile float*)&g_invS) = inv;
            __threadfence();
            atomicAdd(&g_release, 1ULL);
        }
        __syncthreads();
    }

    const float invS = s_invS;

    // ======================= phase 2: scale + write ========================
    // Same block-stride chunks as phase 1, REVERSE order (warm cache first).
    const int nmine = (nchunks > blockIdx.x)
                    ? ((nchunks - blockIdx.x + GRID - 1) / GRID) : 0;
    for (int i = nmine - 1; i >= 0; i--) {
        const int sc = blockIdx.x + i * GRID;
        const int base = sc * EPB;
        if (sc > 0 && base + EPB + 5 <= n) {
            float4 c[VPT];
            #pragma unroll
            for (int j = 0; j < VPT; j++) {
                const int v = base + j * (TPB * 4) + tid * 4;
                c[j] = __ldg(reinterpret_cast<const float4*>(f + v));
            }
            #pragma unroll
            for (int j = 0; j < VPT; j++) {
                const int v = base + j * (TPB * 4) + tid * 4;
                float m3 = __shfl_up_sync(FULL, c[j].y, 1);
                float m2 = __shfl_up_sync(FULL, c[j].z, 1);
                float m1 = __shfl_up_sync(FULL, c[j].w, 1);
                float p4 = __shfl_down_sync(FULL, c[j].x, 1);
                float p5 = __shfl_down_sync(FULL, c[j].y, 1);
                if (lane == 0) {
                    m3 = __ldg(f + v - 3);
                    m2 = __ldg(f + v - 2);
                    m1 = __ldg(f + v - 1);
                }
                if (lane == 31) {
                    p4 = __ldg(f + v + 4);
                    p5 = __ldg(f + v + 5);
                }
                float d0 = (m3     - c[j].z) * 0.2f;
                float d1 = (m2     - c[j].w) * 0.2f;
                float d2 = (m1     - p4    ) * 0.2f;
                float d3 = (c[j].x - p5    ) * 0.2f;
                float t0 = 1.0f - d0 * d0 * invS;
                float t1 = 1.0f - d1 * d1 * invS;
                float t2 = 1.0f - d2 * d2 * invS;
                float t3 = 1.0f - d3 * d3 * invS;
                float q0 = t0 * t0, q1 = t1 * t1, q2 = t2 * t2, q3 = t3 * t3;
                float4 o;
                o.x = q0 * q0 * t0 * c[j].x;
                o.y = q1 * q1 * t1 * c[j].y;
                o.z = q2 * q2 * t2 * c[j].z;
                o.w = q3 * q3 * t3 * c[j].w;
                __stcs(reinterpret_cast<float4*>(out + v), o);
            }
        } else {
            #pragma unroll
            for (int j = 0; j < VPT; j++) {
                const int v = base + j * (TPB * 4) + tid * 4;
                if (v + 3 < n) {
                    float4 c = __ldg(reinterpret_cast<const float4*>(f + v));
                    float m3 = (v >= 3)    ? __ldg(f + v - 3) : 0.0f;
                    float m2 = (v >= 2)    ? __ldg(f + v - 2) : 0.0f;
                    float m1 = (v >= 1)    ? __ldg(f + v - 1) : 0.0f;
                    float p4 = (v + 4 < n) ? __ldg(f + v + 4) : 0.0f;
                    float p5 = (v + 5 < n) ? __ldg(f + v + 5) : 0.0f;
                    float d0 = (m3  - c.z) * 0.2f;
                    float d1 = (m2  - c.w) * 0.2f;
                    float d2 = (m1  - p4 ) * 0.2f;
                    float d3 = (c.x - p5 ) * 0.2f;
                    float c0 = (v == 0) ? 0.0f : d0 * d0 * invS;
                    float t0 = 1.0f - c0;
                    float t1 = 1.0f - d1 * d1 * invS;
                    float t2 = 1.0f - d2 * d2 * invS;
                    float t3 = 1.0f - d3 * d3 * invS;
                    float q0 = t0 * t0, q1 = t1 * t1, q2 = t2 * t2, q3 = t3 * t3;
                    float4 o;
                    o.x = q0 * q0 * t0 * c.x;
                    o.y = q1 * q1 * t1 * c.y;
                    o.z = q2 * q2 * t2 * c.z;
                    o.w = q3 * q3 * t3 * c.w;
                    __stcs(reinterpret_cast<float4*>(out + v), o);
                } else if (v < n) {
                    for (int k = v; k < n; k++) {
                        float l = (k >= 3)    ? __ldg(f + k - 3) : 0.0f;
                        float r = (k + 2 < n) ? __ldg(f + k + 2) : 0.0f;
                        float d = (l - r) * 0.2f;
                        float ch = (k == 0) ? 0.0f : d * d * invS;
                        float t = 1.0f - ch;
                        float q = t * t;
                        out[k] = q * q * t * __ldg(f + k);
                    }
                }
            }
        }
    }
}

// ---------------------------------------------------------------- launch
extern "C" void kernel_launch(void* const* d_in, const int* in_sizes, int n_in,
                              void* d_out, int out_size) {
    const float* f = (const float*)d_in[0];
    float* out = (float*)d_out;
    int n = in_sizes[0];

    k_fused<<<GRID, TPB>>>(f, out, n);
}